// round 11
// baseline (speedup 1.0000x reference)
#include <cuda_runtime.h>
#include <stdint.h>

#define N_NODES 100000
#define DEG 12
#define CH 64
#define NREL 8

#define M_CTA 128
#define GRID_B ((N_NODES + M_CTA - 1) / M_CTA)    // 782
#define ROWS_PAD (GRID_B * M_CTA)                  // 100096

// scratch: per-(node, rel) gathered sums, tf32 bit patterns.
// zero-initialized at module load; rows >= N_NODES are never written and read as 0.
__device__ uint32_t g_S[(size_t)ROWS_PAD * NREL * CH];

// B fragments, repacked for uint4 loads, /12 folded, tf32:
// g_wt4[((rel*8+kt)*4+nq)*32 + lane] = {nt0.b0, nt0.b1, nt1.b0, nt1.b1}
//   word w: n = nq*16 + (w>>1)*8 + lane/4 ; k = kt*8 + lane%4 + 4*(w&1)
__device__ uint4 g_wt4[NREL * 8 * 4 * 32];

__device__ __forceinline__ uint32_t f2tf32(float f) {
    uint32_t r;
    asm("cvt.rna.tf32.f32 %0, %1;" : "=r"(r) : "f"(f));
    return r;
}

__device__ __forceinline__ void mma_tf32(float* d, const uint32_t* a, uint32_t b0, uint32_t b1) {
    asm volatile("mma.sync.aligned.m16n8k8.row.col.f32.tf32.tf32.f32 "
                 "{%0,%1,%2,%3}, {%4,%5,%6,%7}, {%8,%9}, {%0,%1,%2,%3};"
                 : "+f"(d[0]), "+f"(d[1]), "+f"(d[2]), "+f"(d[3])
                 : "r"(a[0]), "r"(a[1]), "r"(a[2]), "r"(a[3]), "r"(b0), "r"(b1));
}

// ================= kernel A: warp-per-node gather, no smem, no barriers =================
__global__ __launch_bounds__(256, 3)
void gather_kernel(const float* __restrict__ x,
                   const void* __restrict__ ptrv,
                   const void* __restrict__ idxv,
                   const void* __restrict__ etv)
{
    const int lane = threadIdx.x & 31;
    const int node = blockIdx.x * 8 + (threadIdx.x >> 5);
    if (node >= N_NODES) return;

    const bool is64 = (((const int*)ptrv)[1] == 0);   // int64 -> high half of ptr[0]=0

    // lanes 0-11 hold idx[e]; lanes 16-27 hold edge_type[e]<<24
    uint32_t p = 0;
    {
        const int hl = lane & 15;
        if (hl < DEG) {
            if (lane < 16) {
                p = is64 ? (uint32_t)((const long long*)idxv)[(size_t)node * DEG + hl]
                         : ((const uint32_t*)idxv)[node * DEG + hl];
            } else {
                const uint32_t r = is64 ? (uint32_t)((const long long*)etv)[(size_t)node * DEG + hl]
                                        : ((const uint32_t*)etv)[node * DEG + hl];
                p = r << 24;
            }
        }
    }

    // issue all 12 row loads up front (MLP=12); lane covers channel pair 2*lane
    const float* xl = x + 2 * lane;
    uint32_t rl[DEG];
    float2 v[DEG];
    #pragma unroll
    for (int e = 0; e < DEG; ++e) {
        const uint32_t src = __shfl_sync(0xffffffffu, p, e);
        rl[e] = __shfl_sync(0xffffffffu, p, 16 + e) >> 24;
        v[e] = *(const float2*)(xl + (size_t)src * CH);
    }

    // demux: rel is warp-uniform per edge -> predicated adds
    float2 acc[NREL];
    #pragma unroll
    for (int r = 0; r < NREL; ++r) acc[r] = make_float2(0.f, 0.f);
    #pragma unroll
    for (int e = 0; e < DEG; ++e) {
        #pragma unroll
        for (int r = 0; r < NREL; ++r)
            if (rl[e] == (uint32_t)r) { acc[r].x += v[e].x; acc[r].y += v[e].y; }
    }

    // store tf32-converted sums: 8 contiguous 256B warp stores
    uint32_t* Sn = g_S + (size_t)node * (NREL * CH);
    #pragma unroll
    for (int r = 0; r < NREL; ++r) {
        uint2 o;
        o.x = f2tf32(acc[r].x);
        o.y = f2tf32(acc[r].y);
        *(uint2*)(Sn + r * CH + 2 * lane) = o;
    }
}

// ================= kernel B: streaming MMA, out[n] = sum_r Sg[n,r] @ Wt[r] =================
__global__ __launch_bounds__(256)
void mma_kernel(float* __restrict__ out)
{
    const int lane = threadIdx.x & 31, wid = threadIdx.x >> 5;
    const int row0 = blockIdx.x * M_CTA;

    // this warp's 16 rows: row0 + wid*16 + (lane>>2) and +8
    const size_t rowbase = ((size_t)(row0 + wid * 16 + (lane >> 2))) * (NREL * CH) + (lane & 3);

    float d[8][4];   // 8 n-tiles of 8 cols
    #pragma unroll
    for (int nt = 0; nt < 8; ++nt)
        #pragma unroll
        for (int c = 0; c < 4; ++c) d[nt][c] = 0.f;

    #pragma unroll
    for (int rel = 0; rel < NREL; ++rel) {
        #pragma unroll
        for (int kt = 0; kt < 8; ++kt) {
            const size_t base = rowbase + rel * CH + kt * 8;
            uint32_t a[4];
            a[0] = g_S[base];
            a[1] = g_S[base + 8 * (NREL * CH)];
            a[2] = g_S[base + 4];
            a[3] = g_S[base + 8 * (NREL * CH) + 4];
            #pragma unroll
            for (int ng = 0; ng < 4; ++ng) {
                const uint4 b = g_wt4[((rel * 8 + kt) * 4 + ng) * 32 + lane];
                mma_tf32(d[2 * ng],     a, b.x, b.y);
                mma_tf32(d[2 * ng + 1], a, b.z, b.w);
            }
        }
    }

    // epilogue
    const int row = row0 + wid * 16 + (lane >> 2);
    #pragma unroll
    for (int ng = 0; ng < 4; ++ng) {
        #pragma unroll
        for (int h = 0; h < 2; ++h) {
            const int col = ng * 16 + h * 8 + 2 * (lane & 3);
            const float* dd = d[2 * ng + h];
            if (row < N_NODES)
                *(float2*)&out[(size_t)row * CH + col] = make_float2(dd[0], dd[1]);
            if (row + 8 < N_NODES)
                *(float2*)&out[(size_t)(row + 8) * CH + col] = make_float2(dd[2], dd[3]);
        }
    }
}

// ---- weight transform: transpose, /12 fold, tf32, uint4-fragment order ----
__global__ void wt_kernel(const float* __restrict__ lin)
{
    const int i = blockIdx.x * blockDim.x + threadIdx.x;   // 0..32767
    if (i < NREL * 8 * 4 * 32 * 4) {
        const int rel  = i >> 12;
        const int kt   = (i >> 9) & 7;
        const int nq   = (i >> 7) & 3;
        const int lane = (i >> 2) & 31;
        const int w    = i & 3;
        const int n = nq * 16 + ((w >> 1) << 3) + (lane >> 2);
        const int k = kt * 8 + (lane & 3) + 4 * (w & 1);
        ((uint32_t*)g_wt4)[i] = f2tf32(lin[((size_t)rel * CH + k) * CH + n] * (1.0f / 12.0f));
    }
}

extern "C" void kernel_launch(void* const* d_in, const int* in_sizes, int n_in,
                              void* d_out, int out_size)
{
    const float* x   = (const float*)d_in[0];
    const float* lin = (const float*)d_in[1];
    const void*  ptr = d_in[2];
    const void*  idx = d_in[3];
    const void*  et  = d_in[4];
    float* out = (float*)d_out;
    (void)in_sizes; (void)n_in; (void)out_size;

    wt_kernel<<<(NREL * 8 * 4 * 32 * 4 + 255) / 256, 256>>>(lin);
    gather_kernel<<<(N_NODES + 7) / 8, 256>>>(x, ptr, idx, et);
    mma_kernel<<<GRID_B, 256>>>(out);
}